// round 1
// baseline (speedup 1.0000x reference)
#include <cuda_runtime.h>
#include <math.h>

// Problem constants
#define Bn 4
#define Tn 2048
#define Dn 1024
#define Hn 16
#define Kd 64
#define HK 1024   // Hn*Kd

// Scratch (device globals allowed; no cudaMalloc)
__device__ float g_q[Bn * Hn * Tn * Kd];
__device__ float g_k[Bn * Hn * Tn * Kd];
__device__ float g_v[Bn * Hn * Tn * Kd];
__device__ float g_ao[Bn * Tn * HK];

// ---------------------------------------------------------------------------
// Kernel 1: QKV projections.  For each (b,h,which): X[b] (T x D) @ W[h] (D x 64).
// Tile 64x64, BK=16, 256 threads, 4x4 register micro-tile.
// ---------------------------------------------------------------------------
__global__ __launch_bounds__(256, 2) void qkv_kernel(
    const float* __restrict__ X,
    const float* __restrict__ Wq,
    const float* __restrict__ Wk,
    const float* __restrict__ Wv)
{
    __shared__ float As[16][68];  // [d][m], padded
    __shared__ float Bs[16][64];  // [d][n]

    const int mblk  = blockIdx.x;   // 0..T/64-1
    const int bh    = blockIdx.y;   // 0..B*H-1
    const int which = blockIdx.z;   // 0:q 1:k 2:v

    const int b = bh >> 4;
    const int h = bh & 15;

    const float* W = (which == 0) ? Wq : (which == 1) ? Wk : Wv;
    W += (size_t)h * Dn * Kd;
    const float* A = X + (size_t)b * Tn * Dn + (size_t)mblk * 64 * Dn;
    float* out = (which == 0) ? g_q : (which == 1) ? g_k : g_v;
    out += ((size_t)bh * Tn + (size_t)mblk * 64) * Kd;

    const int tid = threadIdx.x;
    const int tx = tid & 15, ty = tid >> 4;
    const int a_m  = tid >> 2;          // 0..63
    const int a_d4 = (tid & 3) << 2;    // 0,4,8,12
    const int b_d  = tid >> 4;          // 0..15
    const int b_n4 = (tid & 15) << 2;   // 0..60

    float acc[4][4] = {};

    for (int kk = 0; kk < Dn; kk += 16) {
        float4 av = *(const float4*)(A + (size_t)a_m * Dn + kk + a_d4);
        float4 bv = *(const float4*)(W + (size_t)(kk + b_d) * Kd + b_n4);
        __syncthreads();
        As[a_d4 + 0][a_m] = av.x;
        As[a_d4 + 1][a_m] = av.y;
        As[a_d4 + 2][a_m] = av.z;
        As[a_d4 + 3][a_m] = av.w;
        *(float4*)&Bs[b_d][b_n4] = bv;
        __syncthreads();
#pragma unroll
        for (int dk = 0; dk < 16; dk++) {
            float4 a4 = *(const float4*)&As[dk][ty << 2];
            float4 b4 = *(const float4*)&Bs[dk][tx << 2];
            float a[4] = {a4.x, a4.y, a4.z, a4.w};
            float bb[4] = {b4.x, b4.y, b4.z, b4.w};
#pragma unroll
            for (int i = 0; i < 4; i++)
#pragma unroll
                for (int j = 0; j < 4; j++)
                    acc[i][j] += a[i] * bb[j];
        }
    }
#pragma unroll
    for (int i = 0; i < 4; i++) {
        float4 r = make_float4(acc[i][0], acc[i][1], acc[i][2], acc[i][3]);
        *(float4*)(out + (size_t)((ty << 2) + i) * Kd + (tx << 2)) = r;
    }
}

// ---------------------------------------------------------------------------
// Kernel 2: causal flash attention. One block = (b,h,64-query tile).
// Online softmax across 64-key tiles; masked tiles skipped (kb <= qb).
// Shared: Qs[64][64], Kst[64][68] (K transposed), Vs[64][64], Ps[64][68].
// ---------------------------------------------------------------------------
__global__ __launch_bounds__(256) void attn_kernel()
{
    extern __shared__ float sm[];
    float* Qs  = sm;                  // 64*64
    float* Kst = Qs + 64 * 64;        // 64*68 : Kst[d*68 + key]
    float* Vs  = Kst + 64 * 68;       // 64*64 : Vs[key*64 + c]
    float* Ps  = Vs + 64 * 64;        // 64*68 : Ps[row*68 + key]

    const int qb = blockIdx.x;        // 0..31
    const int bh = blockIdx.y;        // 0..63
    const int b = bh >> 4;
    const int h = bh & 15;

    const int tid = threadIdx.x;
    const int tx = tid & 15, ty = tid >> 4;

    // Load Q tile (natural layout)
    const float* Qg = g_q + ((size_t)bh * Tn + (size_t)qb * 64) * Kd;
#pragma unroll
    for (int r = 0; r < 4; r++) {
        int idx = tid + r * 256;
        int row = idx >> 4;
        int c4 = (idx & 15) << 2;
        *(float4*)&Qs[row * 64 + c4] = *(const float4*)(Qg + row * 64 + c4);
    }

    float m[4], l[4], o[4][4];
#pragma unroll
    for (int i = 0; i < 4; i++) {
        m[i] = -1e30f;
        l[i] = 0.f;
#pragma unroll
        for (int j = 0; j < 4; j++) o[i][j] = 0.f;
    }

    const int kkey  = tid & 63;
    const int dbase = (tid >> 6) << 4;
    const float SC = 0.125f; // 1/sqrt(64)

    for (int kb = 0; kb <= qb; kb++) {
        const float* Kg = g_k + ((size_t)bh * Tn + (size_t)kb * 64) * Kd;
        const float* Vg = g_v + ((size_t)bh * Tn + (size_t)kb * 64) * Kd;
        __syncthreads();  // previous iteration's PV reads done
        // K transposed into shared (conflict-free compute loads)
#pragma unroll
        for (int q = 0; q < 16; q += 4) {
            float4 kv = *(const float4*)(Kg + kkey * 64 + dbase + q);
            Kst[(dbase + q + 0) * 68 + kkey] = kv.x;
            Kst[(dbase + q + 1) * 68 + kkey] = kv.y;
            Kst[(dbase + q + 2) * 68 + kkey] = kv.z;
            Kst[(dbase + q + 3) * 68 + kkey] = kv.w;
        }
        // V natural layout
#pragma unroll
        for (int r = 0; r < 4; r++) {
            int idx = tid + r * 256;
            int row = idx >> 4;
            int c4 = (idx & 15) << 2;
            *(float4*)&Vs[row * 64 + c4] = *(const float4*)(Vg + row * 64 + c4);
        }
        __syncthreads();

        // S = Q @ K^T  (4x4 per thread)
        float s[4][4] = {};
#pragma unroll 8
        for (int d = 0; d < 64; d++) {
            float4 k4 = *(const float4*)&Kst[d * 68 + (tx << 2)];
            float kk4[4] = {k4.x, k4.y, k4.z, k4.w};
#pragma unroll
            for (int i = 0; i < 4; i++) {
                float qv = Qs[((ty << 2) + i) * 64 + d];
#pragma unroll
                for (int j = 0; j < 4; j++)
                    s[i][j] += qv * kk4[j];
            }
        }

        // scale + causal mask (diagonal tile only)
        if (kb == qb) {
#pragma unroll
            for (int i = 0; i < 4; i++) {
                int rr = (ty << 2) + i;
#pragma unroll
                for (int j = 0; j < 4; j++) {
                    int cc = (tx << 2) + j;
                    s[i][j] = (cc <= rr) ? s[i][j] * SC : -1e30f;
                }
            }
        } else {
#pragma unroll
            for (int i = 0; i < 4; i++)
#pragma unroll
                for (int j = 0; j < 4; j++) s[i][j] *= SC;
        }

        // Online softmax per row. Row r owned by the 16 lanes sharing ty;
        // xor offsets < 16 stay inside the half-warp group.
#pragma unroll
        for (int i = 0; i < 4; i++) {
            float rmax = fmaxf(fmaxf(s[i][0], s[i][1]), fmaxf(s[i][2], s[i][3]));
#pragma unroll
            for (int off = 1; off < 16; off <<= 1)
                rmax = fmaxf(rmax, __shfl_xor_sync(0xffffffffu, rmax, off));
            float mnew = fmaxf(m[i], rmax);
            float corr = __expf(m[i] - mnew);
            m[i] = mnew;
            float rsum = 0.f;
#pragma unroll
            for (int j = 0; j < 4; j++) {
                float p = __expf(s[i][j] - mnew);
                s[i][j] = p;
                rsum += p;
            }
#pragma unroll
            for (int off = 1; off < 16; off <<= 1)
                rsum += __shfl_xor_sync(0xffffffffu, rsum, off);
            l[i] = l[i] * corr + rsum;
#pragma unroll
            for (int j = 0; j < 4; j++) o[i][j] *= corr;
            *(float4*)&Ps[((ty << 2) + i) * 68 + (tx << 2)] =
                make_float4(s[i][0], s[i][1], s[i][2], s[i][3]);
        }
        __syncthreads();

        // O += P @ V
#pragma unroll 8
        for (int ss = 0; ss < 64; ss++) {
            float4 v4 = *(const float4*)&Vs[ss * 64 + (tx << 2)];
            float vv[4] = {v4.x, v4.y, v4.z, v4.w};
#pragma unroll
            for (int i = 0; i < 4; i++) {
                float pv = Ps[((ty << 2) + i) * 68 + ss];
#pragma unroll
                for (int j = 0; j < 4; j++)
                    o[i][j] += pv * vv[j];
            }
        }
    }

    // Epilogue: normalize, write head-major concat layout [B, T, H*K]
    float* Og = g_ao + ((size_t)b * Tn + (size_t)qb * 64) * HK + (size_t)h * Kd;
#pragma unroll
    for (int i = 0; i < 4; i++) {
        float inv = 1.0f / l[i];
        float4 r = make_float4(o[i][0] * inv, o[i][1] * inv,
                               o[i][2] * inv, o[i][3] * inv);
        *(float4*)(Og + (size_t)((ty << 2) + i) * HK + (tx << 2)) = r;
    }
}

// ---------------------------------------------------------------------------
// Kernel 3: output projection Y = AO @ Wo^T + bo.  (8192 x 1024) @ (1024 x 1024)
// ---------------------------------------------------------------------------
__global__ __launch_bounds__(256, 2) void proj_kernel(
    const float* __restrict__ Wo,
    const float* __restrict__ bo,
    float* __restrict__ Y)
{
    __shared__ float As[16][68];  // [c][m]
    __shared__ float Ws[16][68];  // [c][n]  (Wo row n = output col n)

    const int mblk = blockIdx.x;  // 0..127
    const int nblk = blockIdx.y;  // 0..15
    const float* A = g_ao + (size_t)mblk * 64 * HK;

    const int tid = threadIdx.x;
    const int tx = tid & 15, ty = tid >> 4;
    const int a_m  = tid >> 2;
    const int a_c4 = (tid & 3) << 2;

    float acc[4][4] = {};

    for (int kk = 0; kk < HK; kk += 16) {
        float4 av = *(const float4*)(A + (size_t)a_m * HK + kk + a_c4);
        float4 wv = *(const float4*)(Wo + (size_t)(nblk * 64 + a_m) * HK + kk + a_c4);
        __syncthreads();
        As[a_c4 + 0][a_m] = av.x;
        As[a_c4 + 1][a_m] = av.y;
        As[a_c4 + 2][a_m] = av.z;
        As[a_c4 + 3][a_m] = av.w;
        Ws[a_c4 + 0][a_m] = wv.x;
        Ws[a_c4 + 1][a_m] = wv.y;
        Ws[a_c4 + 2][a_m] = wv.z;
        Ws[a_c4 + 3][a_m] = wv.w;
        __syncthreads();
#pragma unroll
        for (int ck = 0; ck < 16; ck++) {
            float4 a4 = *(const float4*)&As[ck][ty << 2];
            float4 w4 = *(const float4*)&Ws[ck][tx << 2];
            float a[4] = {a4.x, a4.y, a4.z, a4.w};
            float w[4] = {w4.x, w4.y, w4.z, w4.w};
#pragma unroll
            for (int i = 0; i < 4; i++)
#pragma unroll
                for (int j = 0; j < 4; j++)
                    acc[i][j] += a[i] * w[j];
        }
    }

    float4 bb = *(const float4*)(bo + nblk * 64 + (tx << 2));
#pragma unroll
    for (int i = 0; i < 4; i++) {
        float4 r = make_float4(acc[i][0] + bb.x, acc[i][1] + bb.y,
                               acc[i][2] + bb.z, acc[i][3] + bb.w);
        *(float4*)(Y + (size_t)(mblk * 64 + (ty << 2) + i) * HK
                     + nblk * 64 + (tx << 2)) = r;
    }
}

// ---------------------------------------------------------------------------
extern "C" void kernel_launch(void* const* d_in, const int* in_sizes, int n_in,
                              void* d_out, int out_size)
{
    (void)in_sizes; (void)n_in; (void)out_size;
    const float* X  = (const float*)d_in[0];
    const float* Wq = (const float*)d_in[1];
    const float* Wk = (const float*)d_in[2];
    const float* Wv = (const float*)d_in[3];
    const float* Wo = (const float*)d_in[4];
    const float* bo = (const float*)d_in[5];
    float* Y = (float*)d_out;

    const int smem = (64 * 64 + 64 * 68 + 64 * 64 + 64 * 68) * (int)sizeof(float); // 67584
    cudaFuncSetAttribute(attn_kernel, cudaFuncAttributeMaxDynamicSharedMemorySize, smem);

    qkv_kernel<<<dim3(Tn / 64, Bn * Hn, 3), 256>>>(X, Wq, Wk, Wv);
    attn_kernel<<<dim3(Tn / 64, Bn * Hn), 256, smem>>>();
    proj_kernel<<<dim3(Bn * Tn / 64, HK / 64), 256>>>(Wo, bo, Y);
}